// round 7
// baseline (speedup 1.0000x reference)
#include <cuda_runtime.h>
#include <math.h>
#include <float.h>

#define DIN   784
#define DH    512
#define DOUT  10
#define BATCH 256

#define NCH   8        // k chunks
#define KCH   98       // DIN / NCH

#define GEMM_BLOCKS 128
#define PREP_BLOCKS 20
#define TOTAL_BLOCKS (GEMM_BLOCKS + PREP_BLOCKS)

#define ASTR  100      // As row stride
#define BSTR  36       // B tile row stride

#define TRI_N 55
#define NACC  75       // 55 mid + 10 amu + 10 aq

// ---------------- device scratch ----------------
__device__ __align__(16) float g_m2[BATCH * DH];    // relu(mu1+b)   (final)
__device__ __align__(16) float g_s2[BATCH * DH];    // gated quad+spb1 (final)
__device__ __align__(16) float g_Ws2[DOUT * DH];
__device__ __align__(16) float g_w2t[DOUT * DH];
__device__ float g_spb2[DOUT];
__device__ float g_klpartA[16];
__device__ float g_klpartB[16];

// ---------------- softplus: fast poly for x < -1, exact fallback ----------------
__device__ __forceinline__ float sp_pair(float x, float& lsp) {
    if (x < -1.0f) {
        float u = __expf(x);
        float P = 1.0f + u * (-0.5f + u * (0.33333334f + u * (-0.25f +
                  u * (0.2f + u * (-0.16666667f + u * 0.14285715f)))));
        float d = P - 1.0f;
        float lp = d * (1.0f + d * (-0.5f + d * (0.33333334f + d * (-0.25f))));
        lsp = x + lp;
        return u * P;
    } else {
        float sp = logf(1.0f + expf(x));
        lsp = logf(sp);
        return sp;
    }
}
__device__ __forceinline__ float sp_only(float x) {
    if (x < -1.0f) {
        float u = __expf(x);
        float P = 1.0f + u * (-0.5f + u * (0.33333334f + u * (-0.25f +
                  u * (0.2f + u * (-0.16666667f + u * 0.14285715f)))));
        return u * P;
    }
    return logf(1.0f + expf(x));
}

// ---------------- K1: full-K dual GEMM, one wave of 148 blocks ----------------
// blocks 0..127: (16 h-tiles x 8 batch-tiles), 32h x 32b each, full K=784 in 8 chunks
// blocks 128..147: layer-2 prep
__global__ __launch_bounds__(256) void k1_mega(const float* __restrict__ x,
                                               const float* __restrict__ w_mu1,
                                               const float* __restrict__ w_sigma1,
                                               const float* __restrict__ b_mu1,
                                               const float* __restrict__ b_sigma1,
                                               const float* __restrict__ w_mu2,
                                               const float* __restrict__ w_sigma2,
                                               const float* __restrict__ b_sigma2) {
    __shared__ __align__(16) float As [32 * ASTR];   // [b][k] natural, stride 100
    __shared__ __align__(16) float B1s[KCH * BSTR];  // [k][h]
    __shared__ __align__(16) float B2s[KCH * BSTR];  // [k][h] softplus'd
    __shared__ float red[8];

    const int tid = threadIdx.x;
    const int id = blockIdx.x;

    if (id >= GEMM_BLOCKS) {
        // ---- prep role ----
        const int pid = id - GEMM_BLOCKS;
        if (pid < 16) {
            float acc = 0.f;
            for (int i = pid * 256 + tid; i < DOUT * DH; i += 16 * 256) {
                float lsp;
                float sp = sp_pair(w_sigma2[i], lsp);
                g_Ws2[i] = sp;
                acc += sp - lsp;
                float v = w_mu2[i];
                acc += v * v;
                g_w2t[(i % DOUT) * DH + (i / DOUT)] = v;
            }
            #pragma unroll
            for (int s = 16; s; s >>= 1) acc += __shfl_xor_sync(0xffffffffu, acc, s);
            if ((tid & 31) == 0) red[tid >> 5] = acc;
            __syncthreads();
            if (tid == 0) {
                float t = 0.f;
                #pragma unroll
                for (int w = 0; w < 8; w++) t += red[w];
                g_klpartB[pid] = t;
            }
        } else if (pid == 16) {
            if (tid < DOUT) g_spb2[tid] = sp_only(b_sigma2[tid]);
        }
        return;
    }

    // ---- GEMM role ----
    const int bt = id & 7;            // batch tile
    const int ht = id >> 3;           // h tile
    const int b0 = bt * 32;
    const int n0 = ht * 32;
    const bool do_kl = (bt == 0);

    const int tx = tid & 15;          // h pair
    const int ty = tid >> 4;          // b pair

    float2 pfa[7];                    // A chunk: 1568 float2 (tid<32 get 7)
    float4 pfb1[4];                   // B1 chunk: 784 float4 (tid<16 get 4)
    float2 pfb2[7];                   // B2 raw chunk: 1568 float2

    float amu00 = 0.f, amu01 = 0.f, amu10 = 0.f, amu11 = 0.f;
    float aq00 = 0.f, aq01 = 0.f, aq10 = 0.f, aq11 = 0.f;
    float klacc = 0.f;

    // prefetch chunk 0
    {
        const int ks = 0;
        #pragma unroll
        for (int j = 0; j < 7; j++) {
            int i = j * 256 + tid;
            if (i < 1568) {
                int r = i / 49, kp = i % 49;
                pfa[j] = *(const float2*)&x[(b0 + r) * DIN + ks + kp * 2];
            }
        }
        #pragma unroll
        for (int j = 0; j < 4; j++) {
            int i = j * 256 + tid;
            if (i < 784) {
                int r = i >> 3, cc = i & 7;
                pfb1[j] = *(const float4*)&w_mu1[(ks + r) * DH + n0 + cc * 4];
            }
        }
        #pragma unroll
        for (int j = 0; j < 7; j++) {
            int i = j * 256 + tid;
            if (i < 1568) {
                int h = i / 49, kp = i % 49;
                pfb2[j] = *(const float2*)&w_sigma1[(n0 + h) * DIN + ks + kp * 2];
            }
        }
    }

    for (int c = 0; c < NCH; c++) {
        // ---- store phase: regs -> smem (+ softplus transform + KL fold) ----
        #pragma unroll
        for (int j = 0; j < 7; j++) {
            int i = j * 256 + tid;
            if (i < 1568) {
                int r = i / 49, kp = i % 49;
                *(float2*)&As[r * ASTR + kp * 2] = pfa[j];
            }
        }
        #pragma unroll
        for (int j = 0; j < 4; j++) {
            int i = j * 256 + tid;
            if (i < 784) {
                int r = i >> 3, cc = i & 7;
                float4 v = pfb1[j];
                *(float4*)&B1s[r * BSTR + cc * 4] = v;
                if (do_kl) klacc += v.x * v.x + v.y * v.y + v.z * v.z + v.w * v.w;
            }
        }
        if (do_kl) {
            #pragma unroll
            for (int j = 0; j < 7; j++) {
                int i = j * 256 + tid;
                if (i < 1568) {
                    int h = i / 49, kp = i % 49;
                    float l0, l1;
                    float s0 = sp_pair(pfb2[j].x, l0);
                    float s1 = sp_pair(pfb2[j].y, l1);
                    klacc += (s0 - l0) + (s1 - l1);
                    B2s[(kp * 2)     * BSTR + h] = s0;
                    B2s[(kp * 2 + 1) * BSTR + h] = s1;
                }
            }
        } else {
            #pragma unroll
            for (int j = 0; j < 7; j++) {
                int i = j * 256 + tid;
                if (i < 1568) {
                    int h = i / 49, kp = i % 49;
                    B2s[(kp * 2)     * BSTR + h] = sp_only(pfb2[j].x);
                    B2s[(kp * 2 + 1) * BSTR + h] = sp_only(pfb2[j].y);
                }
            }
        }
        __syncthreads();

        // ---- prefetch next chunk (global latency hidden under compute) ----
        if (c < NCH - 1) {
            const int ks = (c + 1) * KCH;
            #pragma unroll
            for (int j = 0; j < 7; j++) {
                int i = j * 256 + tid;
                if (i < 1568) {
                    int r = i / 49, kp = i % 49;
                    pfa[j] = *(const float2*)&x[(b0 + r) * DIN + ks + kp * 2];
                }
            }
            #pragma unroll
            for (int j = 0; j < 4; j++) {
                int i = j * 256 + tid;
                if (i < 784) {
                    int r = i >> 3, cc = i & 7;
                    pfb1[j] = *(const float4*)&w_mu1[(ks + r) * DH + n0 + cc * 4];
                }
            }
            #pragma unroll
            for (int j = 0; j < 7; j++) {
                int i = j * 256 + tid;
                if (i < 1568) {
                    int h = i / 49, kp = i % 49;
                    pfb2[j] = *(const float2*)&w_sigma1[(n0 + h) * DIN + ks + kp * 2];
                }
            }
        }

        // ---- compute 98 kk ----
        const float* ap0 = &As[(ty * 2) * ASTR];
        const float* ap1 = ap0 + ASTR;
        #pragma unroll 7
        for (int kk = 0; kk < KCH; kk++) {
            float a0 = ap0[kk];
            float a1 = ap1[kk];
            float2 b1 = *(const float2*)&B1s[kk * BSTR + tx * 2];
            float2 b2 = *(const float2*)&B2s[kk * BSTR + tx * 2];
            float q0 = a0 * a0, q1 = a1 * a1;
            amu00 += a0 * b1.x; amu01 += a0 * b1.y;
            amu10 += a1 * b1.x; amu11 += a1 * b1.y;
            aq00  += q0 * b2.x; aq01  += q0 * b2.y;
            aq10  += q1 * b2.x; aq11  += q1 * b2.y;
        }
        __syncthreads();
    }

    // ---- epilogue: bias + ReLU + spb1, write FINAL m2/s2 ----
    {
        int h0 = n0 + tx * 2;
        float bm0 = b_mu1[h0], bm1 = b_mu1[h0 + 1];
        float sb0 = sp_only(b_sigma1[h0]);
        float sb1 = sp_only(b_sigma1[h0 + 1]);

        float mu0 = amu00 + bm0, mu1 = amu01 + bm1;
        bool g0 = mu0 > 0.f, g1 = mu1 > 0.f;
        float2 m, s;
        m.x = g0 ? mu0 : 0.f;  m.y = g1 ? mu1 : 0.f;
        s.x = g0 ? (aq00 + sb0) : 0.f;  s.y = g1 ? (aq01 + sb1) : 0.f;
        *(float2*)&g_m2[(b0 + ty * 2) * DH + h0] = m;
        *(float2*)&g_s2[(b0 + ty * 2) * DH + h0] = s;

        mu0 = amu10 + bm0; mu1 = amu11 + bm1;
        g0 = mu0 > 0.f; g1 = mu1 > 0.f;
        m.x = g0 ? mu0 : 0.f;  m.y = g1 ? mu1 : 0.f;
        s.x = g0 ? (aq10 + sb0) : 0.f;  s.y = g1 ? (aq11 + sb1) : 0.f;
        *(float2*)&g_m2[(b0 + ty * 2 + 1) * DH + h0] = m;
        *(float2*)&g_s2[(b0 + ty * 2 + 1) * DH + h0] = s;
    }

    if (do_kl) {
        #pragma unroll
        for (int s = 16; s; s >>= 1) klacc += __shfl_xor_sync(0xffffffffu, klacc, s);
        if ((tid & 31) == 0) red[tid >> 5] = klacc;
        __syncthreads();
        if (tid == 0) {
            float t = 0.f;
            #pragma unroll
            for (int w = 0; w < 8; w++) t += red[w];
            g_klpartA[ht] = t;
        }
    }
}

// ---------------- per-warp accumulator strip ----------------
// acc index space: 0..54 = mid (upper-tri o<=p), 55..64 = amu[o], 65..74 = aq[o]
template<int LO, int HI>
__device__ __forceinline__ void accum_strip(const float* __restrict__ m2s,
                                            const float* __restrict__ s2s,
                                            const float* __restrict__ w2s,
                                            float* __restrict__ wp,
                                            int lane) {
    float acc[HI - LO];
    #pragma unroll
    for (int j = 0; j < HI - LO; j++) acc[j] = 0.f;

    #pragma unroll 4
    for (int t = 0; t < DH / 32; t++) {
        int h = t * 32 + lane;
        float m = m2s[h];
        float s = s2s[h];
        float mm = m * m;
        float w[DOUT], sw[DOUT];
        #pragma unroll
        for (int o = 0; o < DOUT; o++) w[o] = w2s[o * DH + h];
        #pragma unroll
        for (int o = 0; o < DOUT; o++) sw[o] = s * w[o];
        {
            int e = 0;
            #pragma unroll
            for (int o = 0; o < DOUT; o++)
                #pragma unroll
                for (int p = o; p < DOUT; p++) {
                    if (e >= LO && e < HI) acc[e - LO] += w[p] * sw[o];
                    e++;
                }
        }
        #pragma unroll
        for (int o = 0; o < DOUT; o++)
            if (TRI_N + o >= LO && TRI_N + o < HI) acc[TRI_N + o - LO] += w[o] * m;
        #pragma unroll
        for (int o = 0; o < DOUT; o++)
            if (65 + o >= LO && 65 + o < HI) acc[65 + o - LO] += __ldg(&g_Ws2[o * DH + h]) * mm;
    }

    #pragma unroll
    for (int s = 16; s; s >>= 1)
        #pragma unroll
        for (int j = 0; j < HI - LO; j++)
            acc[j] += __shfl_xor_sync(0xffffffffu, acc[j], s);

    #pragma unroll
    for (int j = 0; j < HI - LO; j++)
        if (lane == j) wp[LO + j] = acc[j];
}

// ---------------- K2: one block per batch, 128 threads ----------------
__global__ __launch_bounds__(128) void k2_layer2(const float* __restrict__ b_mu2,
                                                 float* __restrict__ out) {
    __shared__ float m2s[DH], s2s[DH];
    __shared__ float w2s[DOUT * DH];
    __shared__ float wp[NACC];
    __shared__ float S[240];
    __shared__ float saq[DOUT];
    __shared__ float kred[4];

    const int tid = threadIdx.x;
    const int warp = tid >> 5, lane = tid & 31;
    const int b = blockIdx.x;

    // ---- phase 1: load final m2/s2 (float4) + stage w2t in smem ----
    *(float4*)&m2s[tid * 4] = *(const float4*)&g_m2[b * DH + tid * 4];
    *(float4*)&s2s[tid * 4] = *(const float4*)&g_s2[b * DH + tid * 4];
    for (int i = tid; i < DOUT * DH / 4; i += 128)
        *(float4*)&w2s[i * 4] = *(const float4*)&g_w2t[i * 4];
    __syncthreads();

    // ---- phase 2: warp-partitioned accumulators ----
    if      (warp == 0) accum_strip< 0, 19>(m2s, s2s, w2s, wp, lane);
    else if (warp == 1) accum_strip<19, 38>(m2s, s2s, w2s, wp, lane);
    else if (warp == 2) accum_strip<38, 57>(m2s, s2s, w2s, wp, lane);
    else                accum_strip<57, 75>(m2s, s2s, w2s, wp, lane);
    __syncthreads();

    // ---- assembly ----
    if (tid < NACC) {
        float v = wp[tid];
        if (tid < TRI_N) {
            int o = 0, rem = tid;
            #pragma unroll
            for (int r = 0; r < DOUT; r++) {
                if (rem >= DOUT - r && o == r) { rem -= DOUT - r; o = r + 1; }
            }
            int p = o + rem;
            S[o * DOUT + p] = v;
            S[p * DOUT + o] = v;
        } else if (tid < 65) {
            int o = tid - TRI_N;
            S[210 + o] = v + __ldg(b_mu2 + o);
        } else {
            saq[tid - 65] = v;
        }
    }
    __syncthreads();
    if (tid < DOUT) {
        // faithful replication of reference's flattened-view trace term
        int n  = DOUT * b + tid;
        int qn = n >> 8;
        int mn = n & 255;
        float trf = g_Ws2[qn * DH + 2 * mn]     * g_s2[mn * DH + mn]
                  + g_Ws2[qn * DH + 2 * mn + 1] * g_s2[mn * DH + 256 + mn];
        S[tid * DOUT + tid] += trf + saq[tid] + g_spb2[tid];
    }
    __syncthreads();

    // ---- softmax + sandwich (warp 0) ----
    if (warp == 0) {
        float v = (lane < DOUT) ? S[210 + lane] : -FLT_MAX;
        float mx = v;
        #pragma unroll
        for (int s = 16; s; s >>= 1) mx = fmaxf(mx, __shfl_xor_sync(0xffffffffu, mx, s));
        float e = (lane < DOUT) ? expf(v - mx) : 0.f;
        float sm = e;
        #pragma unroll
        for (int s = 16; s; s >>= 1) sm += __shfl_xor_sync(0xffffffffu, sm, s);
        if (lane < DOUT) {
            float p = e / sm;
            S[200 + lane] = p;
            out[b * DOUT + lane] = p;
        }
        __syncwarp();

        if (lane < DOUT) {
            float a = 0.f;
            #pragma unroll
            for (int j = 0; j < DOUT; j++) a += S[200 + j] * S[j * DOUT + lane];
            S[220 + lane] = a;
        }
        __syncwarp();
        for (int e2 = lane; e2 < DOUT * DOUT; e2 += 32) {
            int i = e2 / DOUT, k = e2 % DOUT;
            S[100 + e2] = S[200 + i] * (S[e2] - S[220 + k]);
        }
        __syncwarp();
        if (lane < DOUT) {
            float a = 0.f;
            #pragma unroll
            for (int k = 0; k < DOUT; k++) a += S[100 + lane * DOUT + k] * S[200 + k];
            S[230 + lane] = a;
        }
        __syncwarp();
        for (int e2 = lane; e2 < DOUT * DOUT; e2 += 32) {
            int i = e2 / DOUT, l = e2 % DOUT;
            out[BATCH * DOUT + b * DOUT * DOUT + e2] = S[200 + l] * (S[100 + e2] - S[230 + i]);
        }
    }

    // ---- KL finalize (block 0) ----
    if (blockIdx.x == 0) {
        float a = 0.f;
        if (tid < 16) a = g_klpartA[tid] + g_klpartB[tid];
        #pragma unroll
        for (int s = 16; s; s >>= 1) a += __shfl_xor_sync(0xffffffffu, a, s);
        if (lane == 0) kred[warp] = a;
        __syncthreads();
        if (tid == 0)
            out[BATCH * DOUT + BATCH * DOUT * DOUT] =
                0.5f * ((kred[0] + kred[1] + kred[2] + kred[3])
                        - (float)(DH * DIN + DOUT * DH));
    }
}

// ---------------- launch ----------------
extern "C" void kernel_launch(void* const* d_in, const int* in_sizes, int n_in,
                              void* d_out, int out_size) {
    const float* x        = (const float*)d_in[0];
    const float* w_mu1    = (const float*)d_in[1];
    const float* w_sigma1 = (const float*)d_in[2];
    const float* b_mu1    = (const float*)d_in[3];
    const float* b_sigma1 = (const float*)d_in[4];
    const float* w_mu2    = (const float*)d_in[5];
    const float* w_sigma2 = (const float*)d_in[6];
    const float* b_mu2    = (const float*)d_in[7];
    const float* b_sigma2 = (const float*)d_in[8];
    float* out = (float*)d_out;

    k1_mega<<<TOTAL_BLOCKS, 256>>>(x, w_mu1, w_sigma1, b_mu1, b_sigma1,
                                   w_mu2, w_sigma2, b_sigma2);
    k2_layer2<<<BATCH, 128>>>(b_mu2, out);
}

// round 8
// speedup vs baseline: 1.2526x; 1.2526x over previous
#include <cuda_runtime.h>
#include <math.h>
#include <float.h>

#define DIN   784
#define DH    512
#define DOUT  10
#define BATCH 256

#define KC    8        // k-chunks (split-K)
#define KCH   98       // DIN / KC
#define HT    32       // h per tile
#define BT    64       // batch per inner iteration
#define NBT   4        // batch iterations

#define GEMM_BLOCKS 128
#define PREP_BLOCKS 20
#define TOTAL_BLOCKS (GEMM_BLOCKS + PREP_BLOCKS)

#define AS_SZ   (BT * KCH)
#define BPAD    36
#define B_SZ    (KCH * BPAD)
#define SMEM_FLOATS (AS_SZ + 2 * B_SZ)
#define SMEM_BYTES  (SMEM_FLOATS * 4)

#define TRI_N 55
#define NACC  75       // 55 mid + 10 amu + 10 aq

// ---------------- device scratch ----------------
__device__ __align__(16) float g_pmu[KC * BATCH * DH];
__device__ __align__(16) float g_pq [KC * BATCH * DH];
__device__ __align__(16) float g_Ws2[DOUT * DH];
__device__ __align__(16) float g_w2t[DOUT * DH];
__device__ float g_spb1[DH];
__device__ float g_spb2[DOUT];
__device__ float g_klpartA[GEMM_BLOCKS];
__device__ float g_klpartB[16];

// ---------------- softplus: fast poly for x < -1, exact fallback ----------------
__device__ __forceinline__ float sp_pair(float x, float& lsp) {
    if (x < -1.0f) {
        float u = __expf(x);
        float P = 1.0f + u * (-0.5f + u * (0.33333334f + u * (-0.25f +
                  u * (0.2f + u * (-0.16666667f + u * 0.14285715f)))));
        float d = P - 1.0f;
        float lp = d * (1.0f + d * (-0.5f + d * (0.33333334f + d * (-0.25f))));
        lsp = x + lp;
        return u * P;
    } else {
        float sp = logf(1.0f + expf(x));
        lsp = logf(sp);
        return sp;
    }
}
__device__ __forceinline__ float sp_only(float x) {
    if (x < -1.0f) {
        float u = __expf(x);
        float P = 1.0f + u * (-0.5f + u * (0.33333334f + u * (-0.25f +
                  u * (0.2f + u * (-0.16666667f + u * 0.14285715f)))));
        return u * P;
    }
    return logf(1.0f + expf(x));
}

// ---------------- K1 MEGA: one wave of 148 blocks (reverted to R6 structure) ----------------
__global__ __launch_bounds__(256) void k1_mega(const float* __restrict__ x,
                                               const float* __restrict__ w_mu1,
                                               const float* __restrict__ w_sigma1,
                                               const float* __restrict__ b_sigma1,
                                               const float* __restrict__ w_mu2,
                                               const float* __restrict__ w_sigma2,
                                               const float* __restrict__ b_sigma2) {
    extern __shared__ float smem[];
    __shared__ float red[8];
    const int tid = threadIdx.x;
    const int id = blockIdx.x;

    if (id >= GEMM_BLOCKS) {
        const int pid = id - GEMM_BLOCKS;
        if (pid < 16) {
            float acc = 0.f;
            for (int i = pid * 256 + tid; i < DOUT * DH; i += 16 * 256) {
                float lsp;
                float sp = sp_pair(w_sigma2[i], lsp);
                g_Ws2[i] = sp;
                acc += sp - lsp;
                float v = w_mu2[i];
                acc += v * v;
                g_w2t[(i % DOUT) * DH + (i / DOUT)] = v;
            }
            #pragma unroll
            for (int s = 16; s; s >>= 1) acc += __shfl_xor_sync(0xffffffffu, acc, s);
            if ((tid & 31) == 0) red[tid >> 5] = acc;
            __syncthreads();
            if (tid == 0) {
                float t = 0.f;
                #pragma unroll
                for (int w = 0; w < 8; w++) t += red[w];
                g_klpartB[pid] = t;
            }
        } else if (pid == 16) {
            g_spb1[tid]       = sp_only(b_sigma1[tid]);
            g_spb1[tid + 256] = sp_only(b_sigma1[tid + 256]);
        } else if (pid == 17) {
            if (tid < DOUT) g_spb2[tid] = sp_only(b_sigma2[tid]);
        }
        return;
    }

    float* As  = smem;
    float* B1s = smem + AS_SZ;
    float* B2s = B1s + B_SZ;

    const int bx = id & 15;
    const int kc = id >> 4;
    const int n0 = bx * HT;
    const int ks = kc * KCH;

    float klacc = 0.f;

    for (int i = tid; i < KCH * (HT / 4); i += 256) {
        int r = i >> 3, c = i & 7;
        float4 v = *(const float4*)&w_mu1[(ks + r) * DH + n0 + c * 4];
        *(float4*)&B1s[r * BPAD + c * 4] = v;
        klacc += v.x * v.x + v.y * v.y + v.z * v.z + v.w * v.w;
    }
    for (int i = tid; i < HT * (KCH / 2); i += 256) {
        int h = i / 49, kp = i % 49;
        float2 v = *(const float2*)&w_sigma1[(n0 + h) * DIN + ks + kp * 2];
        float l0, l1;
        float s0 = sp_pair(v.x, l0);
        float s1 = sp_pair(v.y, l1);
        klacc += (s0 - l0) + (s1 - l1);
        B2s[(kp * 2)     * BPAD + h] = s0;
        B2s[(kp * 2 + 1) * BPAD + h] = s1;
    }
    #pragma unroll
    for (int s = 16; s; s >>= 1) klacc += __shfl_xor_sync(0xffffffffu, klacc, s);
    if ((tid & 31) == 0) red[tid >> 5] = klacc;
    __syncthreads();
    if (tid == 0) {
        float t = 0.f;
        #pragma unroll
        for (int w = 0; w < 8; w++) t += red[w];
        g_klpartA[id] = t;
    }

    const int tx = tid & 7;
    const int ty = tid >> 3;

    for (int bt = 0; bt < NBT; bt++) {
        const int b0 = bt * BT;
        for (int i = tid; i < BT * (KCH / 2); i += 256) {
            int r = i / 49, kp = i % 49;
            *(float2*)&As[r * KCH + kp * 2] =
                *(const float2*)&x[(b0 + r) * DIN + ks + kp * 2];
        }
        __syncthreads();

        float amu[2][4] = {}, aq[2][4] = {};
        const float* a0p = &As[(ty * 2) * KCH];
        const float* a1p = &As[(ty * 2 + 1) * KCH];

        #pragma unroll 7
        for (int kk = 0; kk < KCH; kk++) {
            float a0 = a0p[kk];
            float a1 = a1p[kk];
            float4 b1 = *(const float4*)&B1s[kk * BPAD + tx * 4];
            float4 b2 = *(const float4*)&B2s[kk * BPAD + tx * 4];
            float q0 = a0 * a0, q1 = a1 * a1;
            amu[0][0] += a0 * b1.x; amu[0][1] += a0 * b1.y;
            amu[0][2] += a0 * b1.z; amu[0][3] += a0 * b1.w;
            amu[1][0] += a1 * b1.x; amu[1][1] += a1 * b1.y;
            amu[1][2] += a1 * b1.z; amu[1][3] += a1 * b1.w;
            aq [0][0] += q0 * b2.x; aq [0][1] += q0 * b2.y;
            aq [0][2] += q0 * b2.z; aq [0][3] += q0 * b2.w;
            aq [1][0] += q1 * b2.x; aq [1][1] += q1 * b2.y;
            aq [1][2] += q1 * b2.z; aq [1][3] += q1 * b2.w;
        }

        #pragma unroll
        for (int i = 0; i < 2; i++) {
            int b = b0 + ty * 2 + i;
            float4 m = make_float4(amu[i][0], amu[i][1], amu[i][2], amu[i][3]);
            float4 q = make_float4(aq [i][0], aq [i][1], aq [i][2], aq [i][3]);
            *(float4*)&g_pmu[(kc * BATCH + b) * DH + n0 + tx * 4] = m;
            *(float4*)&g_pq [(kc * BATCH + b) * DH + n0 + tx * 4] = q;
        }
        __syncthreads();
    }
}

// ---------------- s2 recompute from partials (cross-batch trace gather) ----------------
__device__ __forceinline__ float s2_at(int m, int h, const float* __restrict__ b_mu1) {
    float mu = b_mu1[h];
    #pragma unroll
    for (int c = 0; c < KC; c++) mu += g_pmu[(c * BATCH + m) * DH + h];
    if (mu <= 0.f) return 0.f;
    float q = g_spb1[h];
    #pragma unroll
    for (int c = 0; c < KC; c++) q += g_pq[(c * BATCH + m) * DH + h];
    return q;
}

// ---------------- per-warp accumulator strip over a 256-h half ----------------
// acc index space: 0..54 = mid (upper-tri o<=p), 55..64 = amu[o], 65..74 = aq[o]
template<int LO, int HI>
__device__ __forceinline__ void accum_strip(const float* __restrict__ m2s,
                                            const float* __restrict__ s2s,
                                            const float* __restrict__ w2s,
                                            const float* __restrict__ ws2s,
                                            float* __restrict__ wp,
                                            int h0, int lane) {
    float acc[HI - LO];
    #pragma unroll
    for (int j = 0; j < HI - LO; j++) acc[j] = 0.f;

    #pragma unroll
    for (int t = 0; t < 8; t++) {                 // 8 x 32 = 256 h (one half)
        int h = h0 + t * 32 + lane;
        float m = m2s[h];
        float s = s2s[h];
        float mm = m * m;
        float w[DOUT], sw[DOUT];
        #pragma unroll
        for (int o = 0; o < DOUT; o++) w[o] = w2s[o * DH + h];
        #pragma unroll
        for (int o = 0; o < DOUT; o++) sw[o] = s * w[o];
        {
            int e = 0;
            #pragma unroll
            for (int o = 0; o < DOUT; o++)
                #pragma unroll
                for (int p = o; p < DOUT; p++) {
                    if (e >= LO && e < HI) acc[e - LO] += w[p] * sw[o];
                    e++;
                }
        }
        #pragma unroll
        for (int o = 0; o < DOUT; o++)
            if (TRI_N + o >= LO && TRI_N + o < HI) acc[TRI_N + o - LO] += w[o] * m;
        #pragma unroll
        for (int o = 0; o < DOUT; o++)
            if (65 + o >= LO && 65 + o < HI) acc[65 + o - LO] += ws2s[o * DH + h] * mm;
    }

    #pragma unroll
    for (int s = 16; s; s >>= 1)
        #pragma unroll
        for (int j = 0; j < HI - LO; j++)
            acc[j] += __shfl_xor_sync(0xffffffffu, acc[j], s);

    #pragma unroll
    for (int j = 0; j < HI - LO; j++)
        if (lane == j) wp[LO + j] = acc[j];
}

// ---------------- K2: one block per batch, 256 threads (4 strips x 2 h-halves) ----------------
__global__ __launch_bounds__(256) void k2_layer2(const float* __restrict__ b_mu1,
                                                 const float* __restrict__ b_mu2,
                                                 float* __restrict__ out) {
    __shared__ float m2s[DH], s2s[DH];
    __shared__ float w2s[DOUT * DH];            // 20KB
    __shared__ float ws2s[DOUT * DH];           // 20KB
    __shared__ float wp[2][NACC];
    __shared__ float S[240];
    __shared__ float saq[DOUT];
    __shared__ float kred[8];

    const int tid = threadIdx.x;
    const int warp = tid >> 5, lane = tid & 31;
    const int b = blockIdx.x;
    const int SZ = BATCH * DH;

    // ---- phase 1: combine split-K partials + bias + ReLU; stage w2t & Ws2 ----
    #pragma unroll
    for (int j = 0; j < 2; j++) {
        int h = j * 256 + tid;
        int idx = b * DH + h;
        float mu = __ldg(b_mu1 + h);
        #pragma unroll
        for (int c = 0; c < KC; c++) mu += g_pmu[c * SZ + idx];
        bool gate = (mu > 0.f);
        float s = 0.f;
        if (gate) {
            s = g_spb1[h];
            #pragma unroll
            for (int c = 0; c < KC; c++) s += g_pq[c * SZ + idx];
        }
        m2s[h] = gate ? mu : 0.f;
        s2s[h] = s;
    }
    for (int i = tid; i < DOUT * DH / 4; i += 256) {
        *(float4*)&w2s [i * 4] = *(const float4*)&g_w2t[i * 4];
        *(float4*)&ws2s[i * 4] = *(const float4*)&g_Ws2[i * 4];
    }
    __syncthreads();

    // ---- phase 2: 8 warps = 4 accumulator strips x 2 h-halves ----
    {
        const int half = warp >> 2;
        const int h0 = half * 256;
        float* wpp = wp[half];
        switch (warp & 3) {
            case 0: accum_strip< 0, 19>(m2s, s2s, w2s, ws2s, wpp, h0, lane); break;
            case 1: accum_strip<19, 38>(m2s, s2s, w2s, ws2s, wpp, h0, lane); break;
            case 2: accum_strip<38, 57>(m2s, s2s, w2s, ws2s, wpp, h0, lane); break;
            default: accum_strip<57, 75>(m2s, s2s, w2s, ws2s, wpp, h0, lane); break;
        }
    }
    __syncthreads();

    // ---- assembly: threads 0..74 combine halves and scatter ----
    if (tid < NACC) {
        float v = wp[0][tid] + wp[1][tid];
        if (tid < TRI_N) {
            int o = 0, rem = tid;
            #pragma unroll
            for (int r = 0; r < DOUT; r++) {
                if (rem >= DOUT - r && o == r) { rem -= DOUT - r; o = r + 1; }
            }
            int p = o + rem;
            S[o * DOUT + p] = v;
            S[p * DOUT + o] = v;
        } else if (tid < 65) {
            int o = tid - TRI_N;
            S[210 + o] = v + __ldg(b_mu2 + o);
        } else {
            saq[tid - 65] = v;
        }
    }
    __syncthreads();
    if (tid < DOUT) {
        // faithful replication of reference's flattened-view trace term
        int n  = DOUT * b + tid;
        int qn = n >> 8;
        int mn = n & 255;
        float trf = g_Ws2[qn * DH + 2 * mn]     * s2_at(mn, mn, b_mu1)
                  + g_Ws2[qn * DH + 2 * mn + 1] * s2_at(mn, 256 + mn, b_mu1);
        S[tid * DOUT + tid] += trf + saq[tid] + g_spb2[tid];
    }
    __syncthreads();

    // ---- softmax + sandwich (warp 0) ----
    if (warp == 0) {
        float v = (lane < DOUT) ? S[210 + lane] : -FLT_MAX;
        float mx = v;
        #pragma unroll
        for (int s = 16; s; s >>= 1) mx = fmaxf(mx, __shfl_xor_sync(0xffffffffu, mx, s));
        float e = (lane < DOUT) ? expf(v - mx) : 0.f;
        float sm = e;
        #pragma unroll
        for (int s = 16; s; s >>= 1) sm += __shfl_xor_sync(0xffffffffu, sm, s);
        if (lane < DOUT) {
            float p = e / sm;
            S[200 + lane] = p;
            out[b * DOUT + lane] = p;
        }
        __syncwarp();

        if (lane < DOUT) {
            float a = 0.f;
            #pragma unroll
            for (int j = 0; j < DOUT; j++) a += S[200 + j] * S[j * DOUT + lane];
            S[220 + lane] = a;
        }
        __syncwarp();
        for (int e2 = lane; e2 < DOUT * DOUT; e2 += 32) {
            int i = e2 / DOUT, k = e2 % DOUT;
            S[100 + e2] = S[200 + i] * (S[e2] - S[220 + k]);
        }
        __syncwarp();
        if (lane < DOUT) {
            float a = 0.f;
            #pragma unroll
            for (int k = 0; k < DOUT; k++) a += S[100 + lane * DOUT + k] * S[200 + k];
            S[230 + lane] = a;
        }
        __syncwarp();
        for (int e2 = lane; e2 < DOUT * DOUT; e2 += 32) {
            int i = e2 / DOUT, l = e2 % DOUT;
            out[BATCH * DOUT + b * DOUT * DOUT + e2] = S[200 + l] * (S[100 + e2] - S[230 + i]);
        }
    }

    // ---- KL finalize (block 0) ----
    if (blockIdx.x == 0) {
        float a = 0.f;
        for (int i = tid; i < GEMM_BLOCKS; i += 256) a += g_klpartA[i];
        if (tid < 16) a += g_klpartB[tid];
        #pragma unroll
        for (int s = 16; s; s >>= 1) a += __shfl_xor_sync(0xffffffffu, a, s);
        if (lane == 0) kred[warp] = a;
        __syncthreads();
        if (tid == 0) {
            float t = 0.f;
            #pragma unroll
            for (int w = 0; w < 8; w++) t += kred[w];
            out[BATCH * DOUT + BATCH * DOUT * DOUT] =
                0.5f * (t - (float)(DH * DIN + DOUT * DH));
        }
    }
}

// ---------------- launch ----------------
extern "C" void kernel_launch(void* const* d_in, const int* in_sizes, int n_in,
                              void* d_out, int out_size) {
    const float* x        = (const float*)d_in[0];
    const float* w_mu1    = (const float*)d_in[1];
    const float* w_sigma1 = (const float*)d_in[2];
    const float* b_mu1    = (const float*)d_in[3];
    const float* b_sigma1 = (const float*)d_in[4];
    const float* w_mu2    = (const float*)d_in[5];
    const float* w_sigma2 = (const float*)d_in[6];
    const float* b_mu2    = (const float*)d_in[7];
    const float* b_sigma2 = (const float*)d_in[8];
    float* out = (float*)d_out;

    cudaFuncSetAttribute(k1_mega, cudaFuncAttributeMaxDynamicSharedMemorySize, SMEM_BYTES);
    k1_mega<<<TOTAL_BLOCKS, 256, SMEM_BYTES>>>(x, w_mu1, w_sigma1, b_sigma1,
                                               w_mu2, w_sigma2, b_sigma2);
    k2_layer2<<<BATCH, 256>>>(b_mu1, b_mu2, out);
}

// round 9
// speedup vs baseline: 1.2608x; 1.0065x over previous
#include <cuda_runtime.h>
#include <math.h>
#include <float.h>

#define DIN   784
#define DH    512
#define DOUT  10
#define BATCH 256

#define KC    8        // k-chunks (split-K)
#define KCH   98       // DIN / KC
#define HT    32       // h per tile
#define BT    64       // batch per inner iteration
#define NBT   4        // batch iterations

#define GEMM_BLOCKS 128
#define PREP_BLOCKS 20
#define TOTAL_BLOCKS (GEMM_BLOCKS + PREP_BLOCKS)

#define AS_SZ   (BT * KCH)
#define BPAD    36
#define B_SZ    (KCH * BPAD)
#define SMEM_FLOATS (AS_SZ + 2 * B_SZ)
#define SMEM_BYTES  (SMEM_FLOATS * 4)

#define TRI_N 55
#define NACC  75       // 55 mid + 10 amu + 10 aq

// ---------------- device scratch ----------------
__device__ __align__(16) float g_pmu[KC * BATCH * DH];
__device__ __align__(16) float g_pq [KC * BATCH * DH];
__device__ __align__(16) float g_Ws2[DOUT * DH];
__device__ __align__(16) float g_w2t[DOUT * DH];
__device__ float g_spb1[DH];
__device__ float g_spb2[DOUT];
__device__ float g_klpartA[GEMM_BLOCKS];
__device__ float g_klpartB[16];

// ---------------- packed f32x2 helpers ----------------
__device__ __forceinline__ unsigned long long pack2(float x, float y) {
    unsigned long long r;
    asm("mov.b64 %0, {%1, %2};" : "=l"(r) : "f"(x), "f"(y));
    return r;
}
__device__ __forceinline__ unsigned long long mul2(unsigned long long a, unsigned long long b) {
    unsigned long long r;
    asm("mul.rn.f32x2 %0, %1, %2;" : "=l"(r) : "l"(a), "l"(b));
    return r;
}
__device__ __forceinline__ unsigned long long fma2(unsigned long long a, unsigned long long b,
                                                   unsigned long long c) {
    unsigned long long r;
    asm("fma.rn.f32x2 %0, %1, %2, %3;" : "=l"(r) : "l"(a), "l"(b), "l"(c));
    return r;
}

// ---------------- softplus: fast poly for x < -1, exact fallback ----------------
__device__ __forceinline__ float sp_pair(float x, float& lsp) {
    if (x < -1.0f) {
        float u = __expf(x);
        float P = 1.0f + u * (-0.5f + u * (0.33333334f + u * (-0.25f +
                  u * (0.2f + u * (-0.16666667f + u * 0.14285715f)))));
        float d = P - 1.0f;
        float lp = d * (1.0f + d * (-0.5f + d * (0.33333334f + d * (-0.25f))));
        lsp = x + lp;
        return u * P;
    } else {
        float sp = logf(1.0f + expf(x));
        lsp = logf(sp);
        return sp;
    }
}
__device__ __forceinline__ float sp_only(float x) {
    if (x < -1.0f) {
        float u = __expf(x);
        float P = 1.0f + u * (-0.5f + u * (0.33333334f + u * (-0.25f +
                  u * (0.2f + u * (-0.16666667f + u * 0.14285715f)))));
        return u * P;
    }
    return logf(1.0f + expf(x));
}

// ---------------- K1 MEGA: one wave of 148 blocks, f32x2 inner loop ----------------
__global__ __launch_bounds__(256) void k1_mega(const float* __restrict__ x,
                                               const float* __restrict__ w_mu1,
                                               const float* __restrict__ w_sigma1,
                                               const float* __restrict__ b_sigma1,
                                               const float* __restrict__ w_mu2,
                                               const float* __restrict__ w_sigma2,
                                               const float* __restrict__ b_sigma2) {
    extern __shared__ float smem[];
    __shared__ float red[8];
    const int tid = threadIdx.x;
    const int id = blockIdx.x;

    if (id >= GEMM_BLOCKS) {
        const int pid = id - GEMM_BLOCKS;
        if (pid < 16) {
            float acc = 0.f;
            for (int i = pid * 256 + tid; i < DOUT * DH; i += 16 * 256) {
                float lsp;
                float sp = sp_pair(w_sigma2[i], lsp);
                g_Ws2[i] = sp;
                acc += sp - lsp;
                float v = w_mu2[i];
                acc += v * v;
                g_w2t[(i % DOUT) * DH + (i / DOUT)] = v;
            }
            #pragma unroll
            for (int s = 16; s; s >>= 1) acc += __shfl_xor_sync(0xffffffffu, acc, s);
            if ((tid & 31) == 0) red[tid >> 5] = acc;
            __syncthreads();
            if (tid == 0) {
                float t = 0.f;
                #pragma unroll
                for (int w = 0; w < 8; w++) t += red[w];
                g_klpartB[pid] = t;
            }
        } else if (pid == 16) {
            g_spb1[tid]       = sp_only(b_sigma1[tid]);
            g_spb1[tid + 256] = sp_only(b_sigma1[tid + 256]);
        } else if (pid == 17) {
            if (tid < DOUT) g_spb2[tid] = sp_only(b_sigma2[tid]);
        }
        return;
    }

    float* As  = smem;
    float* B1s = smem + AS_SZ;
    float* B2s = B1s + B_SZ;

    const int bx = id & 15;
    const int kc = id >> 4;
    const int n0 = bx * HT;
    const int ks = kc * KCH;

    float klacc = 0.f;

    for (int i = tid; i < KCH * (HT / 4); i += 256) {
        int r = i >> 3, c = i & 7;
        float4 v = *(const float4*)&w_mu1[(ks + r) * DH + n0 + c * 4];
        *(float4*)&B1s[r * BPAD + c * 4] = v;
        klacc += v.x * v.x + v.y * v.y + v.z * v.z + v.w * v.w;
    }
    for (int i = tid; i < HT * (KCH / 2); i += 256) {
        int h = i / 49, kp = i % 49;
        float2 v = *(const float2*)&w_sigma1[(n0 + h) * DIN + ks + kp * 2];
        float l0, l1;
        float s0 = sp_pair(v.x, l0);
        float s1 = sp_pair(v.y, l1);
        klacc += (s0 - l0) + (s1 - l1);
        B2s[(kp * 2)     * BPAD + h] = s0;
        B2s[(kp * 2 + 1) * BPAD + h] = s1;
    }
    #pragma unroll
    for (int s = 16; s; s >>= 1) klacc += __shfl_xor_sync(0xffffffffu, klacc, s);
    if ((tid & 31) == 0) red[tid >> 5] = klacc;
    __syncthreads();
    if (tid == 0) {
        float t = 0.f;
        #pragma unroll
        for (int w = 0; w < 8; w++) t += red[w];
        g_klpartA[id] = t;
    }

    const int tx = tid & 7;
    const int ty = tid >> 3;

    for (int bt = 0; bt < NBT; bt++) {
        const int b0 = bt * BT;
        for (int i = tid; i < BT * (KCH / 2); i += 256) {
            int r = i / 49, kp = i % 49;
            *(float2*)&As[r * KCH + kp * 2] =
                *(const float2*)&x[(b0 + r) * DIN + ks + kp * 2];
        }
        __syncthreads();

        unsigned long long amu[2][2], aq[2][2];
        amu[0][0] = amu[0][1] = amu[1][0] = amu[1][1] = 0ull;
        aq [0][0] = aq [0][1] = aq [1][0] = aq [1][1] = 0ull;

        const float* a0p = &As[(ty * 2) * KCH];
        const float* a1p = &As[(ty * 2 + 1) * KCH];

        #pragma unroll 7
        for (int kk = 0; kk < KCH; kk++) {
            float a0 = a0p[kk];
            float a1 = a1p[kk];
            ulonglong2 b1 = *(const ulonglong2*)&B1s[kk * BPAD + tx * 4];
            ulonglong2 b2 = *(const ulonglong2*)&B2s[kk * BPAD + tx * 4];
            unsigned long long ap0 = pack2(a0, a0);
            unsigned long long ap1 = pack2(a1, a1);
            unsigned long long q0 = mul2(ap0, ap0);
            unsigned long long q1 = mul2(ap1, ap1);
            amu[0][0] = fma2(ap0, b1.x, amu[0][0]);
            amu[0][1] = fma2(ap0, b1.y, amu[0][1]);
            amu[1][0] = fma2(ap1, b1.x, amu[1][0]);
            amu[1][1] = fma2(ap1, b1.y, amu[1][1]);
            aq [0][0] = fma2(q0,  b2.x, aq [0][0]);
            aq [0][1] = fma2(q0,  b2.y, aq [0][1]);
            aq [1][0] = fma2(q1,  b2.x, aq [1][0]);
            aq [1][1] = fma2(q1,  b2.y, aq [1][1]);
        }

        #pragma unroll
        for (int i = 0; i < 2; i++) {
            int b = b0 + ty * 2 + i;
            ulonglong2 m; m.x = amu[i][0]; m.y = amu[i][1];
            ulonglong2 q; q.x = aq [i][0]; q.y = aq [i][1];
            *(ulonglong2*)&g_pmu[(kc * BATCH + b) * DH + n0 + tx * 4] = m;
            *(ulonglong2*)&g_pq [(kc * BATCH + b) * DH + n0 + tx * 4] = q;
        }
        __syncthreads();
    }
}

// ---------------- s2 recompute from partials (cross-batch trace gather) ----------------
__device__ __forceinline__ float s2_at(int m, int h, const float* __restrict__ b_mu1) {
    float mu = b_mu1[h];
    #pragma unroll
    for (int c = 0; c < KC; c++) mu += g_pmu[(c * BATCH + m) * DH + h];
    if (mu <= 0.f) return 0.f;
    float q = g_spb1[h];
    #pragma unroll
    for (int c = 0; c < KC; c++) q += g_pq[(c * BATCH + m) * DH + h];
    return q;
}

// ---------------- per-warp accumulator strip over a 256-h half, float2 ----------------
// acc index space: 0..54 = mid (upper-tri o<=p), 55..64 = amu[o], 65..74 = aq[o]
template<int LO, int HI>
__device__ __forceinline__ void accum_strip(const float* __restrict__ m2s,
                                            const float* __restrict__ s2s,
                                            const float* __restrict__ w2s,
                                            const float* __restrict__ ws2s,
                                            float* __restrict__ wp,
                                            int h0, int lane) {
    float acc[HI - LO];
    #pragma unroll
    for (int j = 0; j < HI - LO; j++) acc[j] = 0.f;

    #pragma unroll
    for (int t = 0; t < 4; t++) {                 // 4 x 64 = 256 h (one half)
        int h = h0 + t * 64 + lane * 2;
        float2 m = *(const float2*)&m2s[h];
        float2 s = *(const float2*)&s2s[h];
        float2 mm = make_float2(m.x * m.x, m.y * m.y);
        float2 w[DOUT], sw[DOUT];
        #pragma unroll
        for (int o = 0; o < DOUT; o++) w[o] = *(const float2*)&w2s[o * DH + h];
        #pragma unroll
        for (int o = 0; o < DOUT; o++) {
            sw[o].x = s.x * w[o].x;
            sw[o].y = s.y * w[o].y;
        }
        {
            int e = 0;
            #pragma unroll
            for (int o = 0; o < DOUT; o++)
                #pragma unroll
                for (int p = o; p < DOUT; p++) {
                    if (e >= LO && e < HI)
                        acc[e - LO] += w[p].x * sw[o].x + w[p].y * sw[o].y;
                    e++;
                }
        }
        #pragma unroll
        for (int o = 0; o < DOUT; o++)
            if (TRI_N + o >= LO && TRI_N + o < HI)
                acc[TRI_N + o - LO] += w[o].x * m.x + w[o].y * m.y;
        #pragma unroll
        for (int o = 0; o < DOUT; o++)
            if (65 + o >= LO && 65 + o < HI) {
                float2 ws = *(const float2*)&ws2s[o * DH + h];
                acc[65 + o - LO] += ws.x * mm.x + ws.y * mm.y;
            }
    }

    #pragma unroll
    for (int s = 16; s; s >>= 1)
        #pragma unroll
        for (int j = 0; j < HI - LO; j++)
            acc[j] += __shfl_xor_sync(0xffffffffu, acc[j], s);

    #pragma unroll
    for (int j = 0; j < HI - LO; j++)
        if (lane == j) wp[LO + j] = acc[j];
}

// ---------------- K2: one block per batch, 256 threads (4 strips x 2 h-halves) ----------------
__global__ __launch_bounds__(256) void k2_layer2(const float* __restrict__ b_mu1,
                                                 const float* __restrict__ b_mu2,
                                                 float* __restrict__ out) {
    __shared__ float m2s[DH], s2s[DH];
    __shared__ float w2s[DOUT * DH];            // 20KB
    __shared__ float ws2s[DOUT * DH];           // 20KB
    __shared__ float wp[2][NACC];
    __shared__ float S[240];
    __shared__ float saq[DOUT];
    __shared__ float kred[8];

    const int tid = threadIdx.x;
    const int warp = tid >> 5, lane = tid & 31;
    const int b = blockIdx.x;
    const int SZ = BATCH * DH;

    // ---- phase 1: combine split-K partials + bias + ReLU (float2 per thread) ----
    {
        int h = tid * 2;
        int idx = b * DH + h;
        float2 mu = *(const float2*)&b_mu1[h];
        #pragma unroll
        for (int c = 0; c < KC; c++) {
            float2 pv = *(const float2*)&g_pmu[c * SZ + idx];
            mu.x += pv.x; mu.y += pv.y;
        }
        float2 q = *(const float2*)&g_spb1[h];
        #pragma unroll
        for (int c = 0; c < KC; c++) {
            float2 pv = *(const float2*)&g_pq[c * SZ + idx];
            q.x += pv.x; q.y += pv.y;
        }
        bool g0 = mu.x > 0.f, g1 = mu.y > 0.f;
        float2 m, s;
        m.x = g0 ? mu.x : 0.f;  m.y = g1 ? mu.y : 0.f;
        s.x = g0 ? q.x : 0.f;   s.y = g1 ? q.y : 0.f;
        *(float2*)&m2s[h] = m;
        *(float2*)&s2s[h] = s;
    }
    for (int i = tid; i < DOUT * DH / 4; i += 256) {
        *(float4*)&w2s [i * 4] = *(const float4*)&g_w2t[i * 4];
        *(float4*)&ws2s[i * 4] = *(const float4*)&g_Ws2[i * 4];
    }
    __syncthreads();

    // ---- phase 2: 8 warps = 4 accumulator strips x 2 h-halves ----
    {
        const int half = warp >> 2;
        const int h0 = half * 256;
        float* wpp = wp[half];
        switch (warp & 3) {
            case 0: accum_strip< 0, 19>(m2s, s2s, w2s, ws2s, wpp, h0, lane); break;
            case 1: accum_strip<19, 38>(m2s, s2s, w2s, ws2s, wpp, h0, lane); break;
            case 2: accum_strip<38, 57>(m2s, s2s, w2s, ws2s, wpp, h0, lane); break;
            default: accum_strip<57, 75>(m2s, s2s, w2s, ws2s, wpp, h0, lane); break;
        }
    }
    __syncthreads();

    // ---- assembly ----
    if (tid < NACC) {
        float v = wp[0][tid] + wp[1][tid];
        if (tid < TRI_N) {
            int o = 0, rem = tid;
            #pragma unroll
            for (int r = 0; r < DOUT; r++) {
                if (rem >= DOUT - r && o == r) { rem -= DOUT - r; o = r + 1; }
            }
            int p = o + rem;
            S[o * DOUT + p] = v;
            S[p * DOUT + o] = v;
        } else if (tid < 65) {
            int o = tid - TRI_N;
            S[210 + o] = v + __ldg(b_mu2 + o);
        } else {
            saq[tid - 65] = v;
        }
    }
    __syncthreads();
    if (tid < DOUT) {
        // faithful replication of reference's flattened-view trace term
        int n  = DOUT * b + tid;
        int qn = n >> 8;
        int mn = n & 255;
        float trf = g_Ws2[qn * DH + 2 * mn]     * s2_at(mn, mn, b_mu1)
                  + g_Ws2[qn * DH + 2 * mn + 1] * s2_at(mn, 256 + mn, b_mu1);
        S[tid * DOUT + tid] += trf + saq[tid] + g_spb2[tid];
    }
    __syncthreads();

    // ---- softmax + sandwich (warp 0) ----
    if (warp == 0) {
        float v = (lane < DOUT) ? S[210 + lane] : -FLT_MAX;
        float mx = v;
        #pragma unroll
        for (int s = 16; s; s >>= 1) mx = fmaxf(mx, __shfl_xor_sync(0xffffffffu, mx, s));
        float e = (lane < DOUT) ? expf(v - mx) : 0.f;
        float sm = e;
        #pragma unroll
        for (int s = 16; s; s >>= 1) sm += __shfl_xor_sync(0xffffffffu, sm, s);
        if (lane < DOUT) {
            float p = e / sm;
            S[200 + lane] = p;
            out[b * DOUT + lane] = p;
        }
        __syncwarp();

        if (lane < DOUT) {
            float a = 0.f;
            #pragma unroll
            for (int j = 0; j < DOUT; j++) a += S[200 + j] * S[j * DOUT + lane];
            S[220 + lane] = a;
        }
        __syncwarp();
        for (int e2 = lane; e2 < DOUT * DOUT; e2 += 32) {
            int i = e2 / DOUT, k = e2 % DOUT;
            S[100 + e2] = S[200 + i] * (S[e2] - S[220 + k]);
        }
        __syncwarp();
        if (lane < DOUT) {
            float a = 0.f;
            #pragma unroll
            for (int k = 0; k < DOUT; k++) a += S[100 + lane * DOUT + k] * S[200 + k];
            S[230 + lane] = a;
        }
        __syncwarp();
        for (int e2 = lane; e2 < DOUT * DOUT; e2 += 32) {
            int i = e2 / DOUT, l = e2 % DOUT;
            out[BATCH * DOUT + b * DOUT * DOUT + e2] = S[200 + l] * (S[100 + e2] - S[230 + i]);
        }
    }

    // ---- KL finalize (block 0) ----
    if (blockIdx.x == 0) {
        float a = 0.f;
        for (int i = tid; i < GEMM_BLOCKS; i += 256) a += g_klpartA[i];
        if (tid < 16) a += g_klpartB[tid];
        #pragma unroll
        for (int s = 16; s; s >>= 1) a += __shfl_xor_sync(0xffffffffu, a, s);
        if (lane == 0) kred[warp] = a;
        __syncthreads();
        if (tid == 0) {
            float t = 0.f;
            #pragma unroll
            for (int w = 0; w < 8; w++) t += kred[w];
            out[BATCH * DOUT + BATCH * DOUT * DOUT] =
                0.5f * (t - (float)(DH * DIN + DOUT * DH));
        }
    }
}

// ---------------- launch ----------------
extern "C" void kernel_launch(void* const* d_in, const int* in_sizes, int n_in,
                              void* d_out, int out_size) {
    const float* x        = (const float*)d_in[0];
    const float* w_mu1    = (const float*)d_in[1];
    const float* w_sigma1 = (const float*)d_in[2];
    const float* b_mu1    = (const float*)d_in[3];
    const float* b_sigma1 = (const float*)d_in[4];
    const float* w_mu2    = (const float*)d_in[5];
    const float* w_sigma2 = (const float*)d_in[6];
    const float* b_mu2    = (const float*)d_in[7];
    const float* b_sigma2 = (const float*)d_in[8];
    float* out = (float*)d_out;

    cudaFuncSetAttribute(k1_mega, cudaFuncAttributeMaxDynamicSharedMemorySize, SMEM_BYTES);
    k1_mega<<<TOTAL_BLOCKS, 256, SMEM_BYTES>>>(x, w_mu1, w_sigma1, b_sigma1,
                                               w_mu2, w_sigma2, b_sigma2);
    k2_layer2<<<BATCH, 256>>>(b_mu1, b_mu2, out);
}